// round 2
// baseline (speedup 1.0000x reference)
#include <cuda_runtime.h>

// ---------------- problem constants ----------------
#define B_    16
#define H_    56
#define W_    56
#define D_    384
#define NH_   12
#define DH_   32
#define FF_   1536
#define WS_   8
#define HW_   3136          // 56*56
#define TOK_  50176         // B*H*W
#define SCALE_ 0.17677669529663687f  // 1/sqrt(32)

// ---------------- scratch (device globals; no allocs allowed) ----------------
__device__ float g_ln [(size_t)TOK_ * D_];          //  ~77 MB
__device__ float g_big[(size_t)TOK_ * FF_];         // ~308 MB

#define Q_OFF    0                         // TOK*384     = 19,267,584
#define COL_OFF  19267584                  // 784*24576   = 19,267,584
#define R_OFF    38535168                  // 784*384     =    301,056
#define KV_OFF   38836224                  // 784*768     =    602,112
#define PART_OFF 40000000                  // 8*784*384   =  2,408,448

// ---------------- helpers ----------------
__device__ __forceinline__ float block_sum128(float v) {
    __shared__ float sh[4];
    int lane = threadIdx.x & 31, w = threadIdx.x >> 5;
    #pragma unroll
    for (int o = 16; o > 0; o >>= 1) v += __shfl_xor_sync(0xffffffffu, v, o);
    __syncthreads();                 // protect sh across repeated calls
    if (lane == 0) sh[w] = v;
    __syncthreads();
    return sh[0] + sh[1] + sh[2] + sh[3];
}

// ---------------- LayerNorm: one block (128 thr) per token ----------------
__global__ void ln_kernel(const float* __restrict__ x,
                          const float* __restrict__ gam,
                          const float* __restrict__ bet,
                          float* __restrict__ y) {
    size_t t = blockIdx.x;
    const float* xr = x + t * D_;
    float* yr = y + t * D_;
    int tid = threadIdx.x;
    float a = xr[tid], b = xr[tid + 128], c = xr[tid + 256];
    float s = block_sum128(a + b + c);
    float m = s * (1.f / 384.f);
    float da = a - m, db = b - m, dc = c - m;
    float ss = block_sum128(da * da + db * db + dc * dc);
    float rstd = rsqrtf(ss * (1.f / 384.f) + 1e-6f);
    yr[tid]       = da * rstd * gam[tid]       + bet[tid];
    yr[tid + 128] = db * rstd * gam[tid + 128] + bet[tid + 128];
    yr[tid + 256] = dc * rstd * gam[tid + 256] + bet[tid + 256];
}

// ---------------- generic SGEMM (register-staged pipeline) ----------------
// C[M,N] = A[M,(lda)] (cols [z*K, z*K+K)) @ B + epilogue
// blockIdx.z = split-K chunk; C is offset by z*M*N (z=0 when gridDim.z==1).
// act: 0 = none, 1 = SiLU (applied after bias, before residual).
__global__ __launch_bounds__(256, 1)
void gemm_kernel(const float* __restrict__ A, const float* __restrict__ Bm,
                 const float* __restrict__ bias, const float* __restrict__ res,
                 float* __restrict__ C, int M, int N, int K, int lda, int act) {
    __shared__ float As[16][128];
    __shared__ float Bs[16][132];     // +4 pad avoids some store conflicts
    int tid = threadIdx.x;
    int bm = blockIdx.y * 128, bn = blockIdx.x * 128;
    int s = blockIdx.z;
    A  += (size_t)s * K;             // column offset within lda-strided A
    Bm += (size_t)s * K * N;
    C  += (size_t)s * M * N;
    int tx = tid & 15, ty = tid >> 4;

    // per-thread fixed load coordinates
    int a_row0 = (tid)        >> 2, a_c0 = ((tid)        & 3) << 2;
    int a_row1 = (tid + 256)  >> 2, a_c1 = ((tid + 256)  & 3) << 2;
    int b_row0 = (tid)        >> 5, b_c0 = ((tid)        & 31) << 2;
    int b_row1 = (tid + 256)  >> 5, b_c1 = ((tid + 256)  & 31) << 2;
    int am0 = bm + a_row0, am1 = bm + a_row1;

    float acc[8][8];
    #pragma unroll
    for (int i = 0; i < 8; i++)
        #pragma unroll
        for (int j = 0; j < 8; j++) acc[i][j] = 0.f;

    float4 ra0, ra1, rb0, rb1;
    // prologue: load tile 0
    ra0 = (am0 < M) ? *(const float4*)(A + (size_t)am0 * lda + a_c0)
                    : make_float4(0.f, 0.f, 0.f, 0.f);
    ra1 = (am1 < M) ? *(const float4*)(A + (size_t)am1 * lda + a_c1)
                    : make_float4(0.f, 0.f, 0.f, 0.f);
    rb0 = *(const float4*)(Bm + (size_t)b_row0 * N + bn + b_c0);
    rb1 = *(const float4*)(Bm + (size_t)b_row1 * N + bn + b_c1);

    int nt = K >> 4;
    for (int kt = 0; kt < nt; kt++) {
        // store staged regs -> smem
        As[a_c0][a_row0] = ra0.x; As[a_c0 + 1][a_row0] = ra0.y;
        As[a_c0 + 2][a_row0] = ra0.z; As[a_c0 + 3][a_row0] = ra0.w;
        As[a_c1][a_row1] = ra1.x; As[a_c1 + 1][a_row1] = ra1.y;
        As[a_c1 + 2][a_row1] = ra1.z; As[a_c1 + 3][a_row1] = ra1.w;
        *(float4*)(&Bs[b_row0][b_c0]) = rb0;
        *(float4*)(&Bs[b_row1][b_c1]) = rb1;
        __syncthreads();

        // stage next tile loads (overlap with compute)
        if (kt + 1 < nt) {
            int k0 = (kt + 1) << 4;
            ra0 = (am0 < M) ? *(const float4*)(A + (size_t)am0 * lda + k0 + a_c0)
                            : make_float4(0.f, 0.f, 0.f, 0.f);
            ra1 = (am1 < M) ? *(const float4*)(A + (size_t)am1 * lda + k0 + a_c1)
                            : make_float4(0.f, 0.f, 0.f, 0.f);
            rb0 = *(const float4*)(Bm + (size_t)(k0 + b_row0) * N + bn + b_c0);
            rb1 = *(const float4*)(Bm + (size_t)(k0 + b_row1) * N + bn + b_c1);
        }

        #pragma unroll
        for (int k = 0; k < 16; k++) {
            float af[8], bf[8];
            *(float4*)(af)     = *(const float4*)(&As[k][ty * 4]);
            *(float4*)(af + 4) = *(const float4*)(&As[k][64 + ty * 4]);
            *(float4*)(bf)     = *(const float4*)(&Bs[k][tx * 4]);
            *(float4*)(bf + 4) = *(const float4*)(&Bs[k][64 + tx * 4]);
            #pragma unroll
            for (int i = 0; i < 8; i++)
                #pragma unroll
                for (int j = 0; j < 8; j++) acc[i][j] += af[i] * bf[j];
        }
        __syncthreads();
    }

    #pragma unroll
    for (int ii = 0; ii < 8; ii++) {
        int m = bm + (ii < 4 ? ty * 4 + ii : 64 + ty * 4 + ii - 4);
        if (m >= M) continue;
        #pragma unroll
        for (int jj = 0; jj < 2; jj++) {
            int n = bn + jj * 64 + tx * 4;
            float4 v;
            v.x = acc[ii][jj * 4];     v.y = acc[ii][jj * 4 + 1];
            v.z = acc[ii][jj * 4 + 2]; v.w = acc[ii][jj * 4 + 3];
            if (bias) {
                float4 bb = *(const float4*)(bias + n);
                v.x += bb.x; v.y += bb.y; v.z += bb.z; v.w += bb.w;
            }
            if (act == 1) {
                v.x = v.x / (1.f + __expf(-v.x));
                v.y = v.y / (1.f + __expf(-v.y));
                v.z = v.z / (1.f + __expf(-v.z));
                v.w = v.w / (1.f + __expf(-v.w));
            }
            if (res) {
                float4 rr = *(const float4*)(res + (size_t)m * N + n);
                v.x += rr.x; v.y += rr.y; v.z += rr.z; v.w += rr.w;
            }
            *(float4*)(C + (size_t)m * N + n) = v;
        }
    }
}

// ---------------- local window attention ----------------
// block = (batch, window, head); 64 threads = 64 queries of an 8x8 window.
__global__ __launch_bounds__(64)
void lattn_kernel(const float* __restrict__ qkv, float* __restrict__ out) {
    int bid = blockIdx.x;
    int head = bid % NH_;
    int wi = (bid / NH_) % 49;
    int b = bid / (NH_ * 49);
    int wh = wi / 7, ww = wi % 7;
    int t = threadIdx.x;
    int h = wh * 8 + (t >> 3), w = ww * 8 + (t & 7);
    size_t base = ((size_t)(b * H_ + h) * W_ + w) * (3 * D_);

    __shared__ float ks[64][32], vs[64][32];
    __shared__ float ss[64][65];

    float q[32];
    #pragma unroll
    for (int i = 0; i < 32; i += 4) {
        float4 x4 = *(const float4*)(qkv + base + head * 32 + i);
        q[i] = x4.x; q[i + 1] = x4.y; q[i + 2] = x4.z; q[i + 3] = x4.w;
        *(float4*)(&ks[t][i]) = *(const float4*)(qkv + base + D_ + head * 32 + i);
        *(float4*)(&vs[t][i]) = *(const float4*)(qkv + base + 2 * D_ + head * 32 + i);
    }
    __syncthreads();

    float mx = -1e30f;
    for (int kk = 0; kk < 64; kk++) {
        float sc = 0.f;
        #pragma unroll
        for (int i = 0; i < 32; i++) sc += q[i] * ks[kk][i];
        sc *= SCALE_;
        ss[t][kk] = sc;
        mx = fmaxf(mx, sc);
    }
    float sum = 0.f;
    for (int kk = 0; kk < 64; kk++) {
        float e = __expf(ss[t][kk] - mx);
        ss[t][kk] = e;
        sum += e;
    }
    float inv = 1.f / sum;
    float o[32];
    #pragma unroll
    for (int i = 0; i < 32; i++) o[i] = 0.f;
    for (int kk = 0; kk < 64; kk++) {
        float p = ss[t][kk];
        #pragma unroll
        for (int i = 0; i < 32; i++) o[i] += p * vs[kk][i];
    }
    size_t ob = ((size_t)(b * H_ + h) * W_ + w) * D_ + head * 32;
    #pragma unroll
    for (int i = 0; i < 32; i += 4) {
        float4 v4;
        v4.x = o[i] * inv; v4.y = o[i + 1] * inv;
        v4.z = o[i + 2] * inv; v4.w = o[i + 3] * inv;
        *(float4*)(out + ob + i) = v4;
    }
}

// ---------------- global attention (49 reduced KV tokens) ----------------
__global__ __launch_bounds__(128)
void gattn_kernel(const float* __restrict__ q, const float* __restrict__ kv,
                  float* __restrict__ out) {
    int b = blockIdx.z, nh = blockIdx.y, ch = blockIdx.x;
    int tid = threadIdx.x;
    __shared__ float ks[49][32], vs[49][32];
    for (int idx = tid; idx < 49 * 32; idx += 128) {
        int l = idx >> 5, i = idx & 31;
        size_t kb = (size_t)(b * 49 + l) * (2 * D_) + nh * 32;
        ks[l][i] = kv[kb + i];
        vs[l][i] = kv[kb + D_ + i];
    }
    __syncthreads();
    int qi = ch * 128 + tid;
    if (qi >= HW_) return;
    size_t qb = ((size_t)b * HW_ + qi) * D_ + nh * 32;
    float qr[32];
    #pragma unroll
    for (int i = 0; i < 32; i += 4) {
        float4 x4 = *(const float4*)(q + qb + i);
        qr[i] = x4.x; qr[i + 1] = x4.y; qr[i + 2] = x4.z; qr[i + 3] = x4.w;
    }
    float sarr[49];
    float mx = -1e30f;
    for (int l = 0; l < 49; l++) {
        float d = 0.f;
        #pragma unroll
        for (int i = 0; i < 32; i++) d += qr[i] * ks[l][i];
        d *= SCALE_;
        sarr[l] = d;
        mx = fmaxf(mx, d);
    }
    float sum = 0.f;
    for (int l = 0; l < 49; l++) { sarr[l] = __expf(sarr[l] - mx); sum += sarr[l]; }
    float inv = 1.f / sum;
    float o[32];
    #pragma unroll
    for (int i = 0; i < 32; i++) o[i] = 0.f;
    for (int l = 0; l < 49; l++) {
        float p = sarr[l];
        #pragma unroll
        for (int i = 0; i < 32; i++) o[i] += p * vs[l][i];
    }
    #pragma unroll
    for (int i = 0; i < 32; i += 4) {
        float4 v4;
        v4.x = o[i] * inv; v4.y = o[i + 1] * inv;
        v4.z = o[i + 2] * inv; v4.w = o[i + 3] * inv;
        *(float4*)(out + qb + i) = v4;
    }
}

// ---------------- im2col for the 8x8 stride-8 conv (pure permutation) -------
__global__ void im2col_kernel(const float* __restrict__ x, float* __restrict__ col) {
    size_t idx = (size_t)blockIdx.x * 256 + threadIdx.x;
    if (idx >= (size_t)784 * 24576) return;
    int c = (int)(idx % 384);
    size_t t2 = idx / 384;
    int dd = (int)(t2 & 63);
    int dx = dd & 7, dy = dd >> 3;
    size_t p = t2 >> 6;
    int j = (int)(p % 7);
    size_t t4 = p / 7;
    int i2 = (int)(t4 % 7);
    int b = (int)(t4 / 7);
    col[idx] = x[(((size_t)b * 56 + i2 * 8 + dy) * 56 + j * 8 + dx) * 384 + c];
}

// ---------------- conv split-K reduce (+bias) ----------------
__global__ void convred_kernel(const float* __restrict__ part,
                               const float* __restrict__ bias,
                               float* __restrict__ r) {
    int idx = blockIdx.x * 256 + threadIdx.x;
    if (idx >= 784 * 384) return;
    float s = bias[idx % 384];
    #pragma unroll
    for (int i = 0; i < 8; i++) s += part[(size_t)i * 301056 + idx];
    r[idx] = s;
}

// ---------------- host-side launch helpers ----------------
static inline void gemm(const float* A, const float* Bm, const float* bias,
                        const float* res, float* C, int M, int N, int K, int act) {
    dim3 g(N / 128, (M + 127) / 128, 1);
    gemm_kernel<<<g, 256>>>(A, Bm, bias, res, C, M, N, K, K, act);
}

extern "C" void kernel_launch(void* const* d_in, const int* in_sizes, int n_in,
                              void* d_out, int out_size) {
    const float* x      = (const float*)d_in[0];
    const float* g1     = (const float*)d_in[1];
    const float* be1    = (const float*)d_in[2];
    const float* w_qkv  = (const float*)d_in[3];
    const float* b_qkv  = (const float*)d_in[4];
    const float* w_lo   = (const float*)d_in[5];
    const float* b_lo   = (const float*)d_in[6];
    const float* g2     = (const float*)d_in[7];
    const float* be2    = (const float*)d_in[8];
    const float* w_f1l  = (const float*)d_in[9];
    const float* b_f1l  = (const float*)d_in[10];
    const float* w_f2l  = (const float*)d_in[11];
    const float* b_f2l  = (const float*)d_in[12];
    const float* g3     = (const float*)d_in[13];
    const float* be3    = (const float*)d_in[14];
    const float* w_q    = (const float*)d_in[15];
    const float* w_kv   = (const float*)d_in[16];
    const float* conv_w = (const float*)d_in[17];
    const float* conv_b = (const float*)d_in[18];
    const float* w_go   = (const float*)d_in[19];
    const float* b_go   = (const float*)d_in[20];
    const float* g4     = (const float*)d_in[21];
    const float* be4    = (const float*)d_in[22];
    const float* w_f1g  = (const float*)d_in[23];
    const float* b_f1g  = (const float*)d_in[24];
    const float* w_f2g  = (const float*)d_in[25];
    const float* b_f2g  = (const float*)d_in[26];
    float* out = (float*)d_out;

    float *ln, *big;
    cudaGetSymbolAddress((void**)&ln, g_ln);
    cudaGetSymbolAddress((void**)&big, g_big);
    float* qbuf = big + Q_OFF;
    float* colb = big + COL_OFF;
    float* rbuf = big + R_OFF;
    float* kvb  = big + KV_OFF;
    float* part = big + PART_OFF;

    // ---- local attention branch ----
    ln_kernel<<<TOK_, 128>>>(x, g1, be1, ln);
    gemm(ln, w_qkv, b_qkv, nullptr, big, TOK_, 3 * D_, D_, 0);     // qkv
    lattn_kernel<<<B_ * 49 * NH_, 64>>>(big, ln);                  // windows
    gemm(ln, w_lo, b_lo, x, out, TOK_, D_, D_, 0);                 // out1 = x + attn@Wo

    // ---- local FFN ----
    ln_kernel<<<TOK_, 128>>>(out, g2, be2, ln);
    gemm(ln, w_f1l, b_f1l, nullptr, big, TOK_, FF_, D_, 1);        // silu
    gemm(big, w_f2l, b_f2l, out, out, TOK_, D_, FF_, 0);           // out2

    // ---- global attention branch ----
    ln_kernel<<<TOK_, 128>>>(out, g3, be3, ln);
    gemm(ln, w_q, nullptr, nullptr, qbuf, TOK_, D_, D_, 0);        // q
    im2col_kernel<<<(19267584 + 255) / 256, 256>>>(ln, colb);      // im2col
    {   // conv as split-K GEMM: [784, 24576] @ [24576, 384], 8 K-chunks
        dim3 g(3, 7, 8);
        gemm_kernel<<<g, 256>>>(colb, conv_w, nullptr, nullptr, part,
                                784, 384, 3072, 24576, 0);
        convred_kernel<<<(784 * 384 + 255) / 256, 256>>>(part, conv_b, rbuf);
    }
    gemm(rbuf, w_kv, nullptr, nullptr, kvb, 784, 2 * D_, D_, 0);   // kv
    {
        dim3 g(25, NH_, B_);
        gattn_kernel<<<g, 128>>>(qbuf, kvb, ln);
    }
    gemm(ln, w_go, b_go, out, out, TOK_, D_, D_, 0);               // out3

    // ---- global FFN ----
    ln_kernel<<<TOK_, 128>>>(out, g4, be4, ln);
    gemm(ln, w_f1g, b_f1g, nullptr, big, TOK_, FF_, D_, 1);
    gemm(big, w_f2g, b_f2g, out, out, TOK_, D_, FF_, 0);           // final
}

// round 4
// speedup vs baseline: 2.4648x; 2.4648x over previous
#include <cuda_runtime.h>

// ---------------- problem constants ----------------
#define B_    16
#define H_    56
#define W_    56
#define D_    384
#define NH_   12
#define DH_   32
#define FF_   1536
#define WS_   8
#define HW_   3136          // 56*56
#define TOK_  50176         // B*H*W
#define SCALE_ 0.17677669529663687f  // 1/sqrt(32)

// ---------------- scratch (device globals; no allocs allowed) ----------------
__device__ float g_ln [(size_t)TOK_ * D_];          //  ~77 MB
__device__ float g_big[(size_t)TOK_ * FF_];         // ~308 MB

#define Q_OFF    0                         // TOK*384     = 19,267,584
#define COL_OFF  19267584                  // 784*24576   = 19,267,584
#define R_OFF    38535168                  // 784*384     =    301,056
#define KV_OFF   38836224                  // 784*768     =    602,112
#define PART_OFF 40000000                  // 8*784*384   =  2,408,448

// ---------------- helpers ----------------
__device__ __forceinline__ float block_sum128(float v) {
    __shared__ float sh[4];
    int lane = threadIdx.x & 31, w = threadIdx.x >> 5;
    #pragma unroll
    for (int o = 16; o > 0; o >>= 1) v += __shfl_xor_sync(0xffffffffu, v, o);
    __syncthreads();
    if (lane == 0) sh[w] = v;
    __syncthreads();
    return sh[0] + sh[1] + sh[2] + sh[3];
}

__device__ __forceinline__ unsigned tf32r(float x) {
    unsigned u;
    asm("cvt.rna.tf32.f32 %0, %1;" : "=r"(u) : "f"(x));
    return u;
}

// ---------------- LayerNorm: one block (128 thr) per token ----------------
__global__ void ln_kernel(const float* __restrict__ x,
                          const float* __restrict__ gam,
                          const float* __restrict__ bet,
                          float* __restrict__ y) {
    size_t t = blockIdx.x;
    const float* xr = x + t * D_;
    float* yr = y + t * D_;
    int tid = threadIdx.x;
    float a = xr[tid], b = xr[tid + 128], c = xr[tid + 256];
    float s = block_sum128(a + b + c);
    float m = s * (1.f / 384.f);
    float da = a - m, db = b - m, dc = c - m;
    float ss = block_sum128(da * da + db * db + dc * dc);
    float rstd = rsqrtf(ss * (1.f / 384.f) + 1e-6f);
    yr[tid]       = da * rstd * gam[tid]       + bet[tid];
    yr[tid + 128] = db * rstd * gam[tid + 128] + bet[tid + 128];
    yr[tid + 256] = dc * rstd * gam[tid + 256] + bet[tid + 256];
}

// ---------------- tf32 tensor-core GEMM ----------------
// C[M,N] = A[M,lda] (cols [z*K, z*K+K)) @ B + epilogue
// 128x128 block tile, BK=16, 8 warps each 64x32, mma.m16n8k8 tf32.
// act: 0 = none, 1 = SiLU (after bias, before residual).
#define AS_STRIDE 20
#define BS_STRIDE 136
__global__ __launch_bounds__(256)
void gemm_kernel(const float* __restrict__ A, const float* __restrict__ Bm,
                 const float* __restrict__ bias, const float* __restrict__ res,
                 float* __restrict__ C, int M, int N, int K, int lda, int act) {
    __shared__ unsigned As[128 * AS_STRIDE];   // [m][k] m-major, pad->20
    __shared__ unsigned Bs[16 * BS_STRIDE];    // [k][n] k-major, pad->136
    int tid = threadIdx.x;
    int lane = tid & 31, wid = tid >> 5;
    int bm = blockIdx.y * 128, bn = blockIdx.x * 128;
    int s = blockIdx.z;
    A  += (size_t)s * K;
    Bm += (size_t)s * K * N;
    C  += (size_t)s * M * N;

    int wm = (wid >> 2) * 64;       // 0 / 64
    int wn = (wid & 3) * 32;        // 0,32,64,96
    int qid = lane >> 2;            // 0..7
    int qtid = lane & 3;            // 0..3

    // cooperative load coordinates (A: 512 float4 -> 2 per thread)
    int a_row0 = tid >> 1;                  // 0..127
    int a_c0 = (tid & 1) * 8;               // 0 or 8 (two float4 per row half)
    int b_row0 = tid >> 5, b_c0 = (tid & 31) << 2;
    int b_row1 = (tid + 256) >> 5, b_c1 = ((tid + 256) & 31) << 2;
    int am0 = bm + a_row0;

    float acc[4][4][4];
    #pragma unroll
    for (int mi = 0; mi < 4; mi++)
        #pragma unroll
        for (int ni = 0; ni < 4; ni++)
            #pragma unroll
            for (int r = 0; r < 4; r++) acc[mi][ni][r] = 0.f;

    float4 ra0, ra1, rb0, rb1;
    ra0 = (am0 < M) ? *(const float4*)(A + (size_t)am0 * lda + a_c0)
                    : make_float4(0.f, 0.f, 0.f, 0.f);
    ra1 = (am0 < M) ? *(const float4*)(A + (size_t)am0 * lda + a_c0 + 4)
                    : make_float4(0.f, 0.f, 0.f, 0.f);
    rb0 = *(const float4*)(Bm + (size_t)b_row0 * N + bn + b_c0);
    rb1 = *(const float4*)(Bm + (size_t)b_row1 * N + bn + b_c1);

    int nt = K >> 4;
    for (int kt = 0; kt < nt; kt++) {
        // regs -> smem (convert to tf32 with round-to-nearest)
        unsigned* ap = &As[a_row0 * AS_STRIDE + a_c0];
        ap[0] = tf32r(ra0.x); ap[1] = tf32r(ra0.y);
        ap[2] = tf32r(ra0.z); ap[3] = tf32r(ra0.w);
        ap[4] = tf32r(ra1.x); ap[5] = tf32r(ra1.y);
        ap[6] = tf32r(ra1.z); ap[7] = tf32r(ra1.w);
        unsigned* bp0 = &Bs[b_row0 * BS_STRIDE + b_c0];
        bp0[0] = tf32r(rb0.x); bp0[1] = tf32r(rb0.y);
        bp0[2] = tf32r(rb0.z); bp0[3] = tf32r(rb0.w);
        unsigned* bp1 = &Bs[b_row1 * BS_STRIDE + b_c1];
        bp1[0] = tf32r(rb1.x); bp1[1] = tf32r(rb1.y);
        bp1[2] = tf32r(rb1.z); bp1[3] = tf32r(rb1.w);
        __syncthreads();

        // stage next tile (overlap with tensor compute)
        if (kt + 1 < nt) {
            int k0 = (kt + 1) << 4;
            ra0 = (am0 < M) ? *(const float4*)(A + (size_t)am0 * lda + k0 + a_c0)
                            : make_float4(0.f, 0.f, 0.f, 0.f);
            ra1 = (am0 < M) ? *(const float4*)(A + (size_t)am0 * lda + k0 + a_c0 + 4)
                            : make_float4(0.f, 0.f, 0.f, 0.f);
            rb0 = *(const float4*)(Bm + (size_t)(k0 + b_row0) * N + bn + b_c0);
            rb1 = *(const float4*)(Bm + (size_t)(k0 + b_row1) * N + bn + b_c1);
        }

        #pragma unroll
        for (int ks = 0; ks < 16; ks += 8) {
            unsigned afr[4][4], bfr[4][2];
            #pragma unroll
            for (int mi = 0; mi < 4; mi++) {
                int row = wm + mi * 16 + qid;
                afr[mi][0] = As[row * AS_STRIDE + ks + qtid];
                afr[mi][1] = As[(row + 8) * AS_STRIDE + ks + qtid];
                afr[mi][2] = As[row * AS_STRIDE + ks + qtid + 4];
                afr[mi][3] = As[(row + 8) * AS_STRIDE + ks + qtid + 4];
            }
            #pragma unroll
            for (int ni = 0; ni < 4; ni++) {
                int col = wn + ni * 8 + qid;
                bfr[ni][0] = Bs[(ks + qtid) * BS_STRIDE + col];
                bfr[ni][1] = Bs[(ks + qtid + 4) * BS_STRIDE + col];
            }
            #pragma unroll
            for (int mi = 0; mi < 4; mi++)
                #pragma unroll
                for (int ni = 0; ni < 4; ni++) {
                    asm volatile(
                        "mma.sync.aligned.m16n8k8.row.col.f32.tf32.tf32.f32 "
                        "{%0,%1,%2,%3}, {%4,%5,%6,%7}, {%8,%9}, {%0,%1,%2,%3};"
                        : "+f"(acc[mi][ni][0]), "+f"(acc[mi][ni][1]),
                          "+f"(acc[mi][ni][2]), "+f"(acc[mi][ni][3])
                        : "r"(afr[mi][0]), "r"(afr[mi][1]),
                          "r"(afr[mi][2]), "r"(afr[mi][3]),
                          "r"(bfr[ni][0]), "r"(bfr[ni][1]));
                }
        }
        __syncthreads();
    }

    // ---------------- epilogue ----------------
    #pragma unroll
    for (int mi = 0; mi < 4; mi++) {
        #pragma unroll
        for (int half = 0; half < 2; half++) {
            int m = bm + wm + mi * 16 + qid + half * 8;
            if (m >= M) continue;
            #pragma unroll
            for (int ni = 0; ni < 4; ni++) {
                int n = bn + wn + ni * 8 + 2 * qtid;
                float v0 = acc[mi][ni][half * 2];
                float v1 = acc[mi][ni][half * 2 + 1];
                if (bias) { v0 += bias[n]; v1 += bias[n + 1]; }
                if (act == 1) {
                    v0 = v0 / (1.f + __expf(-v0));
                    v1 = v1 / (1.f + __expf(-v1));
                }
                if (res) {
                    const float2 rr = *(const float2*)(res + (size_t)m * N + n);
                    v0 += rr.x; v1 += rr.y;
                }
                float2 o2; o2.x = v0; o2.y = v1;
                *(float2*)(C + (size_t)m * N + n) = o2;
            }
        }
    }
}

// ---------------- local window attention ----------------
__global__ __launch_bounds__(64)
void lattn_kernel(const float* __restrict__ qkv, float* __restrict__ out) {
    int bid = blockIdx.x;
    int head = bid % NH_;
    int wi = (bid / NH_) % 49;
    int b = bid / (NH_ * 49);
    int wh = wi / 7, ww = wi % 7;
    int t = threadIdx.x;
    int h = wh * 8 + (t >> 3), w = ww * 8 + (t & 7);
    size_t base = ((size_t)(b * H_ + h) * W_ + w) * (3 * D_);

    __shared__ float ks[64][32], vs[64][32];
    __shared__ float ss[64][65];

    float q[32];
    #pragma unroll
    for (int i = 0; i < 32; i += 4) {
        float4 x4 = *(const float4*)(qkv + base + head * 32 + i);
        q[i] = x4.x; q[i + 1] = x4.y; q[i + 2] = x4.z; q[i + 3] = x4.w;
        *(float4*)(&ks[t][i]) = *(const float4*)(qkv + base + D_ + head * 32 + i);
        *(float4*)(&vs[t][i]) = *(const float4*)(qkv + base + 2 * D_ + head * 32 + i);
    }
    __syncthreads();

    float mx = -1e30f;
    for (int kk = 0; kk < 64; kk++) {
        float sc = 0.f;
        #pragma unroll
        for (int i = 0; i < 32; i++) sc += q[i] * ks[kk][i];
        sc *= SCALE_;
        ss[t][kk] = sc;
        mx = fmaxf(mx, sc);
    }
    float sum = 0.f;
    for (int kk = 0; kk < 64; kk++) {
        float e = __expf(ss[t][kk] - mx);
        ss[t][kk] = e;
        sum += e;
    }
    float inv = 1.f / sum;
    float o[32];
    #pragma unroll
    for (int i = 0; i < 32; i++) o[i] = 0.f;
    for (int kk = 0; kk < 64; kk++) {
        float p = ss[t][kk];
        #pragma unroll
        for (int i = 0; i < 32; i++) o[i] += p * vs[kk][i];
    }
    size_t ob = ((size_t)(b * H_ + h) * W_ + w) * D_ + head * 32;
    #pragma unroll
    for (int i = 0; i < 32; i += 4) {
        float4 v4;
        v4.x = o[i] * inv; v4.y = o[i + 1] * inv;
        v4.z = o[i + 2] * inv; v4.w = o[i + 3] * inv;
        *(float4*)(out + ob + i) = v4;
    }
}

// ---------------- global attention (49 reduced KV tokens) ----------------
__global__ __launch_bounds__(128)
void gattn_kernel(const float* __restrict__ q, const float* __restrict__ kv,
                  float* __restrict__ out) {
    int b = blockIdx.z, nh = blockIdx.y, ch = blockIdx.x;
    int tid = threadIdx.x;
    __shared__ float ks[49][32], vs[49][32];
    for (int idx = tid; idx < 49 * 32; idx += 128) {
        int l = idx >> 5, i = idx & 31;
        size_t kb = (size_t)(b * 49 + l) * (2 * D_) + nh * 32;
        ks[l][i] = kv[kb + i];
        vs[l][i] = kv[kb + D_ + i];
    }
    __syncthreads();
    int qi = ch * 128 + tid;
    if (qi >= HW_) return;
    size_t qb = ((size_t)b * HW_ + qi) * D_ + nh * 32;
    float qr[32];
    #pragma unroll
    for (int i = 0; i < 32; i += 4) {
        float4 x4 = *(const float4*)(q + qb + i);
        qr[i] = x4.x; qr[i + 1] = x4.y; qr[i + 2] = x4.z; qr[i + 3] = x4.w;
    }
    float sarr[49];
    float mx = -1e30f;
    for (int l = 0; l < 49; l++) {
        float d = 0.f;
        #pragma unroll
        for (int i = 0; i < 32; i++) d += qr[i] * ks[l][i];
        d *= SCALE_;
        sarr[l] = d;
        mx = fmaxf(mx, d);
    }
    float sum = 0.f;
    for (int l = 0; l < 49; l++) { sarr[l] = __expf(sarr[l] - mx); sum += sarr[l]; }
    float inv = 1.f / sum;
    float o[32];
    #pragma unroll
    for (int i = 0; i < 32; i++) o[i] = 0.f;
    for (int l = 0; l < 49; l++) {
        float p = sarr[l];
        #pragma unroll
        for (int i = 0; i < 32; i++) o[i] += p * vs[l][i];
    }
    #pragma unroll
    for (int i = 0; i < 32; i += 4) {
        float4 v4;
        v4.x = o[i] * inv; v4.y = o[i + 1] * inv;
        v4.z = o[i + 2] * inv; v4.w = o[i + 3] * inv;
        *(float4*)(out + qb + i) = v4;
    }
}

// ---------------- im2col for the 8x8 stride-8 conv (pure permutation) -------
__global__ void im2col_kernel(const float* __restrict__ x, float* __restrict__ col) {
    size_t idx = (size_t)blockIdx.x * 256 + threadIdx.x;
    if (idx >= (size_t)784 * 24576) return;
    int c = (int)(idx % 384);
    size_t t2 = idx / 384;
    int dd = (int)(t2 & 63);
    int dx = dd & 7, dy = dd >> 3;
    size_t p = t2 >> 6;
    int j = (int)(p % 7);
    size_t t4 = p / 7;
    int i2 = (int)(t4 % 7);
    int b = (int)(t4 / 7);
    col[idx] = x[(((size_t)b * 56 + i2 * 8 + dy) * 56 + j * 8 + dx) * 384 + c];
}

// ---------------- conv split-K reduce (+bias) ----------------
__global__ void convred_kernel(const float* __restrict__ part,
                               const float* __restrict__ bias,
                               float* __restrict__ r) {
    int idx = blockIdx.x * 256 + threadIdx.x;
    if (idx >= 784 * 384) return;
    float s = bias[idx % 384];
    #pragma unroll
    for (int i = 0; i < 8; i++) s += part[(size_t)i * 301056 + idx];
    r[idx] = s;
}

// ---------------- host-side launch helpers ----------------
static inline void gemm(const float* A, const float* Bm, const float* bias,
                        const float* res, float* C, int M, int N, int K, int act) {
    dim3 g(N / 128, (M + 127) / 128, 1);
    gemm_kernel<<<g, 256>>>(A, Bm, bias, res, C, M, N, K, K, act);
}

extern "C" void kernel_launch(void* const* d_in, const int* in_sizes, int n_in,
                              void* d_out, int out_size) {
    const float* x      = (const float*)d_in[0];
    const float* g1     = (const float*)d_in[1];
    const float* be1    = (const float*)d_in[2];
    const float* w_qkv  = (const float*)d_in[3];
    const float* b_qkv  = (const float*)d_in[4];
    const float* w_lo   = (const float*)d_in[5];
    const float* b_lo   = (const float*)d_in[6];
    const float* g2     = (const float*)d_in[7];
    const float* be2    = (const float*)d_in[8];
    const float* w_f1l  = (const float*)d_in[9];
    const float* b_f1l  = (const float*)d_in[10];
    const float* w_f2l  = (const float*)d_in[11];
    const float* b_f2l  = (const float*)d_in[12];
    const float* g3     = (const float*)d_in[13];
    const float* be3    = (const float*)d_in[14];
    const float* w_q    = (const float*)d_in[15];
    const float* w_kv   = (const float*)d_in[16];
    const float* conv_w = (const float*)d_in[17];
    const float* conv_b = (const float*)d_in[18];
    const float* w_go   = (const float*)d_in[19];
    const float* b_go   = (const float*)d_in[20];
    const float* g4     = (const float*)d_in[21];
    const float* be4    = (const float*)d_in[22];
    const float* w_f1g  = (const float*)d_in[23];
    const float* b_f1g  = (const float*)d_in[24];
    const float* w_f2g  = (const float*)d_in[25];
    const float* b_f2g  = (const float*)d_in[26];
    float* out = (float*)d_out;

    float *ln, *big;
    cudaGetSymbolAddress((void**)&ln, g_ln);
    cudaGetSymbolAddress((void**)&big, g_big);
    float* qbuf = big + Q_OFF;
    float* colb = big + COL_OFF;
    float* rbuf = big + R_OFF;
    float* kvb  = big + KV_OFF;
    float* part = big + PART_OFF;

    // ---- local attention branch ----
    ln_kernel<<<TOK_, 128>>>(x, g1, be1, ln);
    gemm(ln, w_qkv, b_qkv, nullptr, big, TOK_, 3 * D_, D_, 0);     // qkv
    lattn_kernel<<<B_ * 49 * NH_, 64>>>(big, ln);                  // windows
    gemm(ln, w_lo, b_lo, x, out, TOK_, D_, D_, 0);                 // out1 = x + attn@Wo

    // ---- local FFN ----
    ln_kernel<<<TOK_, 128>>>(out, g2, be2, ln);
    gemm(ln, w_f1l, b_f1l, nullptr, big, TOK_, FF_, D_, 1);        // silu
    gemm(big, w_f2l, b_f2l, out, out, TOK_, D_, FF_, 0);           // out2

    // ---- global attention branch ----
    ln_kernel<<<TOK_, 128>>>(out, g3, be3, ln);
    gemm(ln, w_q, nullptr, nullptr, qbuf, TOK_, D_, D_, 0);        // q
    im2col_kernel<<<(19267584 + 255) / 256, 256>>>(ln, colb);      // im2col
    {   // conv as split-K GEMM: [784, 24576] @ [24576, 384], 8 K-chunks
        dim3 g(3, 7, 8);
        gemm_kernel<<<g, 256>>>(colb, conv_w, nullptr, nullptr, part,
                                784, 384, 3072, 24576, 0);
        convred_kernel<<<(784 * 384 + 255) / 256, 256>>>(part, conv_b, rbuf);
    }
    gemm(rbuf, w_kv, nullptr, nullptr, kvb, 784, 2 * D_, D_, 0);   // kv
    {
        dim3 g(25, NH_, B_);
        gattn_kernel<<<g, 128>>>(qbuf, kvb, ln);
    }
    gemm(ln, w_go, b_go, out, out, TOK_, D_, D_, 0);               // out3

    // ---- global FFN ----
    ln_kernel<<<TOK_, 128>>>(out, g4, be4, ln);
    gemm(ln, w_f1g, b_f1g, nullptr, big, TOK_, FF_, D_, 1);
    gemm(big, w_f2g, b_f2g, out, out, TOK_, D_, FF_, 0);           // final
}